// round 1
// baseline (speedup 1.0000x reference)
#include <cuda_runtime.h>
#include <float.h>

#define BB 8
#define NN 4096
#define CC 64
#define OO 64
#define KK 20
#define NEG_SLOPE 0.2f
#define EPS 1e-5f
#define DBLK 1024

// ---------------- scratch (no allocations allowed) ----------------
__device__ __align__(16) float g_xT[BB * NN * CC];      // (b, n, c)
__device__ float g_sq[BB * NN];                          // ||x||^2
__device__ __align__(16) float g_p[BB * NN * OO];       // x @ W1^T
__device__ __align__(16) float g_q[BB * NN * OO];       // x @ (W2-W1)^T
__device__ int   g_idx[BB * NN * KK];                    // knn indices (within batch)
__device__ __align__(16) float g_ymax[BB * NN * OO];
__device__ __align__(16) float g_ymin[BB * NN * OO];
__device__ float g_part[DBLK * 2 * OO];                  // per-block BN partials
__device__ float g_stats[2 * OO];                        // [sum(64), sumsq(64)]

// ---------------- A1: transpose (B,C,N) -> (B,N,C) ----------------
__global__ void k_transpose(const float* __restrict__ in) {
    __shared__ float t[32][33];
    int b = blockIdx.z, c0 = blockIdx.y * 32, n0 = blockIdx.x * 32;
    int tx = threadIdx.x, ty = threadIdx.y;  // 32 x 8
#pragma unroll
    for (int j = 0; j < 4; j++)
        t[ty + 8 * j][tx] = in[((size_t)b * CC + (c0 + ty + 8 * j)) * NN + n0 + tx];
    __syncthreads();
#pragma unroll
    for (int j = 0; j < 4; j++)
        g_xT[((size_t)b * NN + (n0 + ty + 8 * j)) * CC + c0 + tx] = t[tx][ty + 8 * j];
}

// ---------------- A2: squared norms + p,q projections ----------------
__global__ void k_pq(const float* __restrict__ W) {
    __shared__ float sWp[OO][CC];
    __shared__ float sWd[OO][CC];
    int tid = threadIdx.x;  // 128
    for (int i = tid; i < OO * CC; i += 128) {
        int o = i >> 6, c = i & 63;
        float wp = W[o * 2 * CC + c];
        sWp[o][c] = wp;
        sWd[o][c] = W[o * 2 * CC + CC + c] - wp;
    }
    __syncthreads();
    int point = blockIdx.x * 128 + tid;
    const float4* xr4 = reinterpret_cast<const float4*>(g_xT + (size_t)point * CC);
    float xr[CC];
    float sq = 0.f;
#pragma unroll
    for (int i = 0; i < 16; i++) {
        float4 v = xr4[i];
        xr[4 * i] = v.x; xr[4 * i + 1] = v.y; xr[4 * i + 2] = v.z; xr[4 * i + 3] = v.w;
        sq = fmaf(v.x, v.x, sq); sq = fmaf(v.y, v.y, sq);
        sq = fmaf(v.z, v.z, sq); sq = fmaf(v.w, v.w, sq);
    }
    g_sq[point] = sq;
    float* pp = g_p + (size_t)point * OO;
    float* qq = g_q + (size_t)point * OO;
#pragma unroll 1
    for (int o = 0; o < OO; o++) {
        const float4* wp4 = reinterpret_cast<const float4*>(&sWp[o][0]);
        const float4* wd4 = reinterpret_cast<const float4*>(&sWd[o][0]);
        float ap = 0.f, aq = 0.f;
#pragma unroll
        for (int i = 0; i < 16; i++) {
            float4 wp = wp4[i], wd = wd4[i];
            ap = fmaf(xr[4 * i], wp.x, ap); ap = fmaf(xr[4 * i + 1], wp.y, ap);
            ap = fmaf(xr[4 * i + 2], wp.z, ap); ap = fmaf(xr[4 * i + 3], wp.w, ap);
            aq = fmaf(xr[4 * i], wd.x, aq); aq = fmaf(xr[4 * i + 1], wd.y, aq);
            aq = fmaf(xr[4 * i + 2], wd.z, aq); aq = fmaf(xr[4 * i + 3], wd.w, aq);
        }
        pp[o] = ap;
        qq[o] = aq;
    }
}

// ---------------- B: fused pairwise-distance + streaming top-20 ----------------
// key(n,m) = 2*dot(x_n,x_m) - ||x_m||^2  (row-constant -||x_n||^2 dropped: same ranking
// as reference pd). Strict '>' insert + ascending m == top_k lower-index tie-break.
#define INSERT(key, mi)                                              \
    {                                                                \
        sBv[kpos][tid] = (key);                                      \
        besti[kpos] = (mi);                                          \
        float mn_ = sBv[0][tid];                                     \
        int mp_ = 0;                                                 \
        _Pragma("unroll") for (int j_ = 1; j_ < KK; j_++) {          \
            float v_ = sBv[j_][tid];                                 \
            if (v_ < mn_) { mn_ = v_; mp_ = j_; }                    \
        }                                                            \
        kth = mn_;                                                   \
        kpos = mp_;                                                  \
    }

__global__ void __launch_bounds__(128) k_knn() {
    __shared__ __align__(16) float smX[CC][128];  // [c][m] tile, 32KB
    __shared__ float smSq[128];
    __shared__ float sBv[KK][128];                // top-20 values, bank-conflict-free
    int b = blockIdx.y;
    int r0 = blockIdx.x * 128;
    int tid = threadIdx.x;  // 128, one query row per thread
    const float* xb = g_xT + (size_t)b * NN * CC;

    float xq[CC];
    {
        const float4* xr = reinterpret_cast<const float4*>(xb + (size_t)(r0 + tid) * CC);
#pragma unroll
        for (int i = 0; i < 16; i++) {
            float4 v = xr[i];
            xq[4 * i] = v.x; xq[4 * i + 1] = v.y; xq[4 * i + 2] = v.z; xq[4 * i + 3] = v.w;
        }
    }

    int besti[KK];
#pragma unroll
    for (int j = 0; j < KK; j++) { sBv[j][tid] = -FLT_MAX; besti[j] = 0; }
    float kth = -FLT_MAX;
    int kpos = 0;

    for (int mt = 0; mt < NN; mt += 128) {
        __syncthreads();
        {   // load candidate tile transposed into smem: smX[c][m_local]
            const float4* mr = reinterpret_cast<const float4*>(xb + (size_t)(mt + tid) * CC);
#pragma unroll
            for (int i = 0; i < 16; i++) {
                float4 v = mr[i];
                smX[4 * i][tid] = v.x; smX[4 * i + 1][tid] = v.y;
                smX[4 * i + 2][tid] = v.z; smX[4 * i + 3][tid] = v.w;
            }
            smSq[tid] = g_sq[b * NN + mt + tid];
        }
        __syncthreads();

#pragma unroll 1
        for (int mm = 0; mm < 128; mm += 4) {
            float a0 = 0.f, a1 = 0.f, a2 = 0.f, a3 = 0.f;
#pragma unroll
            for (int c = 0; c < CC; c++) {
                float4 v = *reinterpret_cast<const float4*>(&smX[c][mm]);
                float q = xq[c];
                a0 = fmaf(q, v.x, a0); a1 = fmaf(q, v.y, a1);
                a2 = fmaf(q, v.z, a2); a3 = fmaf(q, v.w, a3);
            }
            int mb = mt + mm;
            float k0 = 2.f * a0 - smSq[mm];
            float k1 = 2.f * a1 - smSq[mm + 1];
            float k2 = 2.f * a2 - smSq[mm + 2];
            float k3 = 2.f * a3 - smSq[mm + 3];
            if (k0 > kth) INSERT(k0, mb)
            if (k1 > kth) INSERT(k1, mb + 1)
            if (k2 > kth) INSERT(k2, mb + 2)
            if (k3 > kth) INSERT(k3, mb + 3)
        }
    }
    int* op = g_idx + ((size_t)b * NN + r0 + tid) * KK;
#pragma unroll
    for (int j = 0; j < KK; j++) op[j] = besti[j];
}

// ---------------- D: gather p[idx]+q, max/min over k, BN partial sums ----------------
__global__ void k_gather() {
    int tid = threadIdx.x;  // 256
    int g = tid >> 6, o = tid & 63;
    float psum = 0.f, psq = 0.f;
#pragma unroll 1
    for (int i = 0; i < 8; i++) {
        int point = blockIdx.x * 32 + i * 4 + g;
        int b = point >> 12;
        const int* ix = g_idx + (size_t)point * KK;
        float qv = g_q[(size_t)point * OO + o];
        const float* pb = g_p + (((size_t)b) << 12) * OO;
        float mx = -FLT_MAX, mn = FLT_MAX;
#pragma unroll
        for (int k = 0; k < KK; k++) {
            int j = ix[k];
            float y = pb[(size_t)j * OO + o] + qv;
            mx = fmaxf(mx, y);
            mn = fminf(mn, y);
            psum += y;
            psq = fmaf(y, y, psq);
        }
        g_ymax[(size_t)point * OO + o] = mx;
        g_ymin[(size_t)point * OO + o] = mn;
    }
    __shared__ float ss[256], s2[256];
    ss[tid] = psum; s2[tid] = psq;
    __syncthreads();
    if (tid < 64) {
        float a = ss[tid] + ss[tid + 64] + ss[tid + 128] + ss[tid + 192];
        float c = s2[tid] + s2[tid + 64] + s2[tid + 128] + s2[tid + 192];
        g_part[(size_t)blockIdx.x * 128 + tid] = a;
        g_part[(size_t)blockIdx.x * 128 + 64 + tid] = c;
    }
}

// ---------------- D2: deterministic reduction of BN partials ----------------
__global__ void k_reduce() {
    int i = blockIdx.x;  // 0..127
    int t = threadIdx.x; // 256
    float s = 0.f;
    for (int blk = t; blk < DBLK; blk += 256) s += g_part[(size_t)blk * 128 + i];
    __shared__ float sm[256];
    sm[t] = s;
    __syncthreads();
    for (int w = 128; w > 0; w >>= 1) {
        if (t < w) sm[t] += sm[t + w];
        __syncthreads();
    }
    if (t == 0) g_stats[i] = sm[0];
}

// ---------------- E: BN + LeakyReLU (commuted past max) + transpose out ----------------
__global__ void k_out(const float* __restrict__ gamma, const float* __restrict__ beta,
                      float* __restrict__ out) {
    __shared__ float smT[OO][33];
    int b = blockIdx.y, n0 = blockIdx.x * 32;
    int tid = threadIdx.x;  // 256
    const float CNTf = (float)(BB * NN * KK);
#pragma unroll 1
    for (int i = tid; i < 32 * OO; i += 256) {
        int n = i >> 6, o = i & 63;
        float s = g_stats[o], s2v = g_stats[64 + o];
        float mean = s / CNTf;
        float var = s2v / CNTf - mean * mean;
        float rstd = rsqrtf(var + EPS);
        float gm = gamma[o];
        size_t yi = ((size_t)b * NN + n0 + n) * OO + o;
        float v = (gm >= 0.f) ? g_ymax[yi] : g_ymin[yi];
        float z = gm * (v - mean) * rstd + beta[o];
        z = (z >= 0.f) ? z : NEG_SLOPE * z;
        smT[o][n] = z;
    }
    __syncthreads();
#pragma unroll 1
    for (int i = tid; i < OO * 32; i += 256) {
        int o = i >> 5, n = i & 31;
        out[((size_t)b * OO + o) * NN + n0 + n] = smT[o][n];
    }
}

extern "C" void kernel_launch(void* const* d_in, const int* in_sizes, int n_in,
                              void* d_out, int out_size) {
    const float* inp = (const float*)d_in[0];
    const float* W = (const float*)d_in[1];
    const float* gamma = (const float*)d_in[2];
    const float* beta = (const float*)d_in[3];
    float* out = (float*)d_out;

    k_transpose<<<dim3(NN / 32, CC / 32, BB), dim3(32, 8)>>>(inp);
    k_pq<<<BB * NN / 128, 128>>>(W);
    k_knn<<<dim3(NN / 128, BB), 128>>>();
    k_gather<<<DBLK, 256>>>();
    k_reduce<<<2 * OO, 256>>>();
    k_out<<<dim3(NN / 32, BB), 256>>>(gamma, beta, out);
}

// round 2
// speedup vs baseline: 1.1436x; 1.1436x over previous
#include <cuda_runtime.h>
#include <float.h>

#define BB 8
#define NN 4096
#define CC 64
#define OO 64
#define KK 20
#define NEG_SLOPE 0.2f
#define EPS 1e-5f
#define DBLK 1024
#define MSUB 16

typedef unsigned long long ull;

__device__ __forceinline__ ull pack2(float lo, float hi) {
    ull r; asm("mov.b64 %0, {%1, %2};" : "=l"(r) : "f"(lo), "f"(hi)); return r;
}
__device__ __forceinline__ void unpack2(ull v, float &lo, float &hi) {
    asm("mov.b64 {%0, %1}, %2;" : "=f"(lo), "=f"(hi) : "l"(v));
}
__device__ __forceinline__ void ffma2(ull &d, ull a, ull b) {
    asm("fma.rn.f32x2 %0, %1, %2, %3;" : "=l"(d) : "l"(a), "l"(b), "l"(d));
}

// ---------------- scratch (no allocations allowed) ----------------
__device__ __align__(16) float g_xT[BB * NN * CC];      // (b, n, c)
__device__ float g_sq[BB * NN];                          // ||x||^2
__device__ __align__(16) float g_p[BB * NN * OO];       // x @ W1^T
__device__ __align__(16) float g_q[BB * NN * OO];       // x @ (W2-W1)^T
__device__ int   g_idx[BB * NN * KK];                    // knn indices (within batch)
__device__ __align__(16) float g_ymax[BB * NN * OO];
__device__ __align__(16) float g_ymin[BB * NN * OO];
__device__ float g_part[DBLK * 2 * OO];                  // per-block BN partials
__device__ float g_stats[2 * OO];                        // [sum(64), sumsq(64)]

// ---------------- A1: transpose (B,C,N) -> (B,N,C) ----------------
__global__ void k_transpose(const float* __restrict__ in) {
    __shared__ float t[32][33];
    int b = blockIdx.z, c0 = blockIdx.y * 32, n0 = blockIdx.x * 32;
    int tx = threadIdx.x, ty = threadIdx.y;  // 32 x 8
#pragma unroll
    for (int j = 0; j < 4; j++)
        t[ty + 8 * j][tx] = in[((size_t)b * CC + (c0 + ty + 8 * j)) * NN + n0 + tx];
    __syncthreads();
#pragma unroll
    for (int j = 0; j < 4; j++)
        g_xT[((size_t)b * NN + (n0 + ty + 8 * j)) * CC + c0 + tx] = t[tx][ty + 8 * j];
}

// ---------------- A2: squared norms + p,q projections ----------------
__global__ void k_pq(const float* __restrict__ W) {
    __shared__ float sWp[OO][CC];
    __shared__ float sWd[OO][CC];
    int tid = threadIdx.x;  // 128
    for (int i = tid; i < OO * CC; i += 128) {
        int o = i >> 6, c = i & 63;
        float wp = W[o * 2 * CC + c];
        sWp[o][c] = wp;
        sWd[o][c] = W[o * 2 * CC + CC + c] - wp;
    }
    __syncthreads();
    int point = blockIdx.x * 128 + tid;
    const float4* xr4 = reinterpret_cast<const float4*>(g_xT + (size_t)point * CC);
    float xr[CC];
    float sq = 0.f;
#pragma unroll
    for (int i = 0; i < 16; i++) {
        float4 v = xr4[i];
        xr[4 * i] = v.x; xr[4 * i + 1] = v.y; xr[4 * i + 2] = v.z; xr[4 * i + 3] = v.w;
        sq = fmaf(v.x, v.x, sq); sq = fmaf(v.y, v.y, sq);
        sq = fmaf(v.z, v.z, sq); sq = fmaf(v.w, v.w, sq);
    }
    g_sq[point] = sq;
    float* pp = g_p + (size_t)point * OO;
    float* qq = g_q + (size_t)point * OO;
#pragma unroll 1
    for (int o = 0; o < OO; o++) {
        const float4* wp4 = reinterpret_cast<const float4*>(&sWp[o][0]);
        const float4* wd4 = reinterpret_cast<const float4*>(&sWd[o][0]);
        float ap = 0.f, aq = 0.f;
#pragma unroll
        for (int i = 0; i < 16; i++) {
            float4 wp = wp4[i], wd = wd4[i];
            ap = fmaf(xr[4 * i], wp.x, ap); ap = fmaf(xr[4 * i + 1], wp.y, ap);
            ap = fmaf(xr[4 * i + 2], wp.z, ap); ap = fmaf(xr[4 * i + 3], wp.w, ap);
            aq = fmaf(xr[4 * i], wd.x, aq); aq = fmaf(xr[4 * i + 1], wd.y, aq);
            aq = fmaf(xr[4 * i + 2], wd.z, aq); aq = fmaf(xr[4 * i + 3], wd.w, aq);
        }
        pp[o] = ap;
        qq[o] = aq;
    }
}

// ---------------- B: fused pairwise-distance (packed f32x2) + streaming top-20 ----
// key(n,m) = 2*dot(x_n,x_m) - ||x_m||^2  (row-constant -||x_n||^2 dropped: same ranking
// as reference pd). Strict '>' keeps the lower-index element on ties; only the SET of
// 20 indices matters downstream (max over k + sums), so insertion order is irrelevant.
__global__ void __launch_bounds__(128, 3) k_knn() {
    __shared__ __align__(16) ull smX2[32][128];   // pair (c, c+32) per candidate: 32KB
    __shared__ float smSq[128];
    __shared__ float sBv[KK][128];                // top-20 values     (10KB)
    __shared__ int   sBi[KK][128];                // top-20 indices    (10KB)
    __shared__ float sKey[MSUB][128];             // per-subtile keys  (8KB)
    int b = blockIdx.y;
    int r0 = blockIdx.x * 128;
    int tid = threadIdx.x;  // one query row per thread
    const float* xb = g_xT + (size_t)b * NN * CC;

    // query row packed over c: xq2[cp] = (x[cp], x[cp+32])
    ull xq2[32];
    {
        const float4* xr = reinterpret_cast<const float4*>(xb + (size_t)(r0 + tid) * CC);
#pragma unroll
        for (int i = 0; i < 8; i++) {
            float4 a = xr[i], c = xr[i + 8];
            xq2[4 * i + 0] = pack2(a.x, c.x);
            xq2[4 * i + 1] = pack2(a.y, c.y);
            xq2[4 * i + 2] = pack2(a.z, c.z);
            xq2[4 * i + 3] = pack2(a.w, c.w);
        }
    }

#pragma unroll
    for (int j = 0; j < KK; j++) { sBv[j][tid] = -FLT_MAX; sBi[j][tid] = 0; }
    float kth = -FLT_MAX;
    int kpos = 0;

    for (int mt = 0; mt < NN; mt += 128) {
        __syncthreads();
        {   // candidate tile, interleaved pairs: smX2[cp][m] = (x[m][cp], x[m][cp+32])
            const float4* mr = reinterpret_cast<const float4*>(xb + (size_t)(mt + tid) * CC);
#pragma unroll
            for (int i = 0; i < 8; i++) {
                float4 a = mr[i], c = mr[i + 8];
                smX2[4 * i + 0][tid] = pack2(a.x, c.x);
                smX2[4 * i + 1][tid] = pack2(a.y, c.y);
                smX2[4 * i + 2][tid] = pack2(a.z, c.z);
                smX2[4 * i + 3][tid] = pack2(a.w, c.w);
            }
            smSq[tid] = g_sq[b * NN + mt + tid];
        }
        __syncthreads();

#pragma unroll 1
        for (int ms = 0; ms < 128; ms += MSUB) {
            ull acc[MSUB];
#pragma unroll
            for (int t = 0; t < MSUB; t++) acc[t] = 0ull;
#pragma unroll 4
            for (int cp = 0; cp < 32; cp++) {
                const ulonglong2* row = reinterpret_cast<const ulonglong2*>(&smX2[cp][ms]);
                ull q = xq2[cp];
#pragma unroll
                for (int t = 0; t < MSUB / 2; t++) {
                    ulonglong2 v = row[t];      // LDS.128, broadcast (2 candidates)
                    ffma2(acc[2 * t], q, v.x);
                    ffma2(acc[2 * t + 1], q, v.y);
                }
            }
            // keys + pending mask
            unsigned pmask = 0;
#pragma unroll
            for (int t = 0; t < MSUB; t++) {
                float lo, hi; unpack2(acc[t], lo, hi);
                float key = fmaf(2.f, lo + hi, -smSq[ms + t]);
                sKey[t][tid] = key;
                if (key > kth) pmask |= (1u << t);
            }
            // converged insert loop: warp iterates max-over-lanes(pending)
            while (__any_sync(0xffffffffu, pmask != 0)) {
                if (pmask) {
                    int t = __ffs(pmask) - 1;
                    pmask &= pmask - 1;
                    float kv = sKey[t][tid];
                    if (kv > kth) {          // re-filter against risen kth
                        sBv[kpos][tid] = kv;
                        sBi[kpos][tid] = mt + ms + t;
                        float mn = sBv[0][tid]; int mp = 0;
#pragma unroll
                        for (int j = 1; j < KK; j++) {
                            float v = sBv[j][tid];
                            if (v < mn) { mn = v; mp = j; }
                        }
                        kth = mn; kpos = mp;
                    }
                }
            }
        }
    }
    int* op = g_idx + ((size_t)b * NN + r0 + tid) * KK;
#pragma unroll
    for (int j = 0; j < KK; j++) op[j] = sBi[j][tid];
}

// ---------------- D: gather p[idx]+q, max/min over k, BN partial sums ----------------
__global__ void k_gather() {
    int tid = threadIdx.x;  // 256
    int g = tid >> 6, o = tid & 63;
    float psum = 0.f, psq = 0.f;
#pragma unroll 1
    for (int i = 0; i < 8; i++) {
        int point = blockIdx.x * 32 + i * 4 + g;
        int b = point >> 12;
        const int* ix = g_idx + (size_t)point * KK;
        float qv = g_q[(size_t)point * OO + o];
        const float* pb = g_p + (((size_t)b) << 12) * OO;
        float mx = -FLT_MAX, mn = FLT_MAX;
#pragma unroll
        for (int k = 0; k < KK; k++) {
            int j = ix[k];
            float y = pb[(size_t)j * OO + o] + qv;
            mx = fmaxf(mx, y);
            mn = fminf(mn, y);
            psum += y;
            psq = fmaf(y, y, psq);
        }
        g_ymax[(size_t)point * OO + o] = mx;
        g_ymin[(size_t)point * OO + o] = mn;
    }
    __shared__ float ss[256], s2[256];
    ss[tid] = psum; s2[tid] = psq;
    __syncthreads();
    if (tid < 64) {
        float a = ss[tid] + ss[tid + 64] + ss[tid + 128] + ss[tid + 192];
        float c = s2[tid] + s2[tid + 64] + s2[tid + 128] + s2[tid + 192];
        g_part[(size_t)blockIdx.x * 128 + tid] = a;
        g_part[(size_t)blockIdx.x * 128 + 64 + tid] = c;
    }
}

// ---------------- D2: deterministic reduction of BN partials ----------------
__global__ void k_reduce() {
    int i = blockIdx.x;  // 0..127
    int t = threadIdx.x; // 256
    float s = 0.f;
    for (int blk = t; blk < DBLK; blk += 256) s += g_part[(size_t)blk * 128 + i];
    __shared__ float sm[256];
    sm[t] = s;
    __syncthreads();
    for (int w = 128; w > 0; w >>= 1) {
        if (t < w) sm[t] += sm[t + w];
        __syncthreads();
    }
    if (t == 0) g_stats[i] = sm[0];
}

// ---------------- E: BN + LeakyReLU (commuted past max) + transpose out ----------------
__global__ void k_out(const float* __restrict__ gamma, const float* __restrict__ beta,
                      float* __restrict__ out) {
    __shared__ float smT[OO][33];
    int b = blockIdx.y, n0 = blockIdx.x * 32;
    int tid = threadIdx.x;  // 256
    const float CNTf = (float)(BB * NN * KK);
#pragma unroll 1
    for (int i = tid; i < 32 * OO; i += 256) {
        int n = i >> 6, o = i & 63;
        float s = g_stats[o], s2v = g_stats[64 + o];
        float mean = s / CNTf;
        float var = s2v / CNTf - mean * mean;
        float rstd = rsqrtf(var + EPS);
        float gm = gamma[o];
        size_t yi = ((size_t)b * NN + n0 + n) * OO + o;
        float v = (gm >= 0.f) ? g_ymax[yi] : g_ymin[yi];
        float z = gm * (v - mean) * rstd + beta[o];
        z = (z >= 0.f) ? z : NEG_SLOPE * z;
        smT[o][n] = z;
    }
    __syncthreads();
#pragma unroll 1
    for (int i = tid; i < OO * 32; i += 256) {
        int o = i >> 5, n = i & 31;
        out[((size_t)b * OO + o) * NN + n0 + n] = smT[o][n];
    }
}

extern "C" void kernel_launch(void* const* d_in, const int* in_sizes, int n_in,
                              void* d_out, int out_size) {
    const float* inp = (const float*)d_in[0];
    const float* W = (const float*)d_in[1];
    const float* gamma = (const float*)d_in[2];
    const float* beta = (const float*)d_in[3];
    float* out = (float*)d_out;

    k_transpose<<<dim3(NN / 32, CC / 32, BB), dim3(32, 8)>>>(inp);
    k_pq<<<BB * NN / 128, 128>>>(W);
    k_knn<<<dim3(NN / 128, BB), 128>>>();
    k_gather<<<DBLK, 256>>>();
    k_reduce<<<2 * OO, 256>>>();
    k_out<<<dim3(NN / 32, BB), 256>>>(gamma, beta, out);
}

// round 5
// speedup vs baseline: 1.6766x; 1.4662x over previous
#include <cuda_runtime.h>
#include <cuda_bf16.h>
#include <float.h>
#include <cstdint>

#define BB 8
#define NN 4096
#define CC 64
#define OO 64
#define KK 20
#define NEG_SLOPE 0.2f
#define EPS 1e-5f
#define DBLK 1024

typedef unsigned long long ull;

// sentinel: packed(-FLT_MAX key, idx decode 0)
#define TOP_SENTINEL 0x00800000FFFFFFFFull

// ---------------- smem map for k_knn_wmma ----------------
#define OFF_A   0                     // 128 x 400B  (192 bf16 + 8 pad)
#define OFF_B   51200                 // 128 x 400B
#define OFF_D   102400                // 8 warps x 16 x 520B
#define OFF_TOP 168960                // SoA: 20 slots x 256 threads x 8B
#define OFF_NSQ 209920                // 128 x 4B
#define DYN_BYTES 210432

__device__ __forceinline__ uint32_t smem_u32(const void* p) {
    uint32_t a;
    asm("{ .reg .u64 t; cvta.to.shared.u64 t, %1; cvt.u32.u64 %0, t; }" : "=r"(a) : "l"(p));
    return a;
}
__device__ __forceinline__ void ldsm4(uint32_t* r, uint32_t addr) {
    asm volatile("ldmatrix.sync.aligned.m8n8.x4.shared.b16 {%0,%1,%2,%3}, [%4];"
        : "=r"(r[0]), "=r"(r[1]), "=r"(r[2]), "=r"(r[3]) : "r"(addr));
}
__device__ __forceinline__ void mma_bf16(float* c, const uint32_t* a, const uint32_t* b) {
    asm volatile(
        "mma.sync.aligned.m16n8k16.row.col.f32.bf16.bf16.f32 "
        "{%0,%1,%2,%3}, {%4,%5,%6,%7}, {%8,%9}, {%0,%1,%2,%3};"
        : "+f"(c[0]), "+f"(c[1]), "+f"(c[2]), "+f"(c[3])
        : "r"(a[0]), "r"(a[1]), "r"(a[2]), "r"(a[3]), "r"(b[0]), "r"(b[1]));
}

// ---------------- scratch ----------------
__device__ __align__(16) float g_xT[BB * NN * CC];
__device__ __align__(16) __nv_bfloat16 g_xs[BB * NN * 128];  // [hi(64)|lo(64)] per point
__device__ float g_sq[BB * NN];
__device__ __align__(16) float g_p[BB * NN * OO];
__device__ __align__(16) float g_q[BB * NN * OO];
__device__ int   g_idx[BB * NN * KK];
__device__ __align__(16) float g_ymax[BB * NN * OO];
__device__ __align__(16) float g_ymin[BB * NN * OO];
__device__ float g_part[DBLK * 2 * OO];
__device__ float g_stats[2 * OO];

// ---------------- A1: transpose (B,C,N) -> (B,N,C) ----------------
__global__ void k_transpose(const float* __restrict__ in) {
    __shared__ float t[32][33];
    int b = blockIdx.z, c0 = blockIdx.y * 32, n0 = blockIdx.x * 32;
    int tx = threadIdx.x, ty = threadIdx.y;
#pragma unroll
    for (int j = 0; j < 4; j++)
        t[ty + 8 * j][tx] = in[((size_t)b * CC + (c0 + ty + 8 * j)) * NN + n0 + tx];
    __syncthreads();
#pragma unroll
    for (int j = 0; j < 4; j++)
        g_xT[((size_t)b * NN + (n0 + ty + 8 * j)) * CC + c0 + tx] = t[tx][ty + 8 * j];
}

// ---------------- A1b: split fp32 -> bf16 hi/lo ----------------
__global__ void k_split() {
    int idx = blockIdx.x * 256 + threadIdx.x;   // BB*NN*4 threads
    int point = idx >> 2, part = idx & 3;
    const float4* src = reinterpret_cast<const float4*>(g_xT + (size_t)point * CC + part * 16);
    union { __nv_bfloat162 h2[8]; uint4 v[2]; } hi, lo;
#pragma unroll
    for (int j = 0; j < 4; j++) {
        float4 v = src[j];
        float f[4] = {v.x, v.y, v.z, v.w};
#pragma unroll
        for (int e = 0; e < 2; e++) {
            float a = f[2 * e], b2 = f[2 * e + 1];
            __nv_bfloat16 ha = __float2bfloat16_rn(a);
            __nv_bfloat16 hb = __float2bfloat16_rn(b2);
            __nv_bfloat16 la = __float2bfloat16_rn(a - __bfloat162float(ha));
            __nv_bfloat16 lb = __float2bfloat16_rn(b2 - __bfloat162float(hb));
            hi.h2[2 * j + e] = __nv_bfloat162(ha, hb);
            lo.h2[2 * j + e] = __nv_bfloat162(la, lb);
        }
    }
    uint4* dhi = reinterpret_cast<uint4*>(g_xs + (size_t)point * 128 + part * 16);
    uint4* dlo = reinterpret_cast<uint4*>(g_xs + (size_t)point * 128 + 64 + part * 16);
    dhi[0] = hi.v[0]; dhi[1] = hi.v[1];
    dlo[0] = lo.v[0]; dlo[1] = lo.v[1];
}

// ---------------- A2: squared norms + p,q projections ----------------
__global__ void k_pq(const float* __restrict__ W) {
    __shared__ float sWp[OO][CC];
    __shared__ float sWd[OO][CC];
    int tid = threadIdx.x;
    for (int i = tid; i < OO * CC; i += 128) {
        int o = i >> 6, c = i & 63;
        float wp = W[o * 2 * CC + c];
        sWp[o][c] = wp;
        sWd[o][c] = W[o * 2 * CC + CC + c] - wp;
    }
    __syncthreads();
    int point = blockIdx.x * 128 + tid;
    const float4* xr4 = reinterpret_cast<const float4*>(g_xT + (size_t)point * CC);
    float xr[CC];
    float sq = 0.f;
#pragma unroll
    for (int i = 0; i < 16; i++) {
        float4 v = xr4[i];
        xr[4 * i] = v.x; xr[4 * i + 1] = v.y; xr[4 * i + 2] = v.z; xr[4 * i + 3] = v.w;
        sq = fmaf(v.x, v.x, sq); sq = fmaf(v.y, v.y, sq);
        sq = fmaf(v.z, v.z, sq); sq = fmaf(v.w, v.w, sq);
    }
    g_sq[point] = sq;
    float* pp = g_p + (size_t)point * OO;
    float* qq = g_q + (size_t)point * OO;
#pragma unroll 1
    for (int o = 0; o < OO; o++) {
        const float4* wp4 = reinterpret_cast<const float4*>(&sWp[o][0]);
        const float4* wd4 = reinterpret_cast<const float4*>(&sWd[o][0]);
        float ap = 0.f, aq = 0.f;
#pragma unroll
        for (int i = 0; i < 16; i++) {
            float4 wp = wp4[i], wd = wd4[i];
            ap = fmaf(xr[4 * i], wp.x, ap); ap = fmaf(xr[4 * i + 1], wp.y, ap);
            ap = fmaf(xr[4 * i + 2], wp.z, ap); ap = fmaf(xr[4 * i + 3], wp.w, ap);
            aq = fmaf(xr[4 * i], wd.x, aq); aq = fmaf(xr[4 * i + 1], wd.y, aq);
            aq = fmaf(xr[4 * i + 2], wd.z, aq); aq = fmaf(xr[4 * i + 3], wd.w, aq);
        }
        pp[o] = ap;
        qq[o] = aq;
    }
}

// ===================== B: HMMA distance GEMM + per-lane top-20 =====================
// A' = [hi|lo|hi], B' = [hi|hi|lo] over K=192 bf16: acc = hi·hi + lo·hi + hi·lo ≈ fp32 dot.
// key = 2*acc - ||x_m||^2; packed 64-bit (orderedKey<<32 | ~idx) reproduces top_k tie-break.
__global__ void __launch_bounds__(256, 1) k_knn_wmma() {
    extern __shared__ __align__(16) char sm[];
    int tid = threadIdx.x;
    int w = tid >> 5, lane = tid & 31;
    int b = blockIdx.y, r0 = blockIdx.x * 128, bbase = b * NN;
    const char* xsrc = (const char*)g_xs;

    // ---- A tile (resident): dst chunk c -> bytes (c>>3)*128 + (c&7)*16 ; src [hi|lo|hi]
#pragma unroll
    for (int i = 0; i < 12; i++) {
        int u = tid + 256 * i;
        int row = u / 24, c = u % 24;
        int so = (((c >= 8) && (c < 16)) ? 128 : 0) + (c & 7) * 16;
        uint4 v = *reinterpret_cast<const uint4*>(xsrc + (size_t)(bbase + r0 + row) * 256 + so);
        *reinterpret_cast<uint4*>(sm + OFF_A + row * 400 + (c >> 3) * 128 + (c & 7) * 16) = v;
    }

    // ---- top-20 state (SoA: slot j at sTop[j*256 + tid], conflict-free) ----
    ull* sTop = reinterpret_cast<ull*>(sm + OFF_TOP);
#pragma unroll
    for (int j = 0; j < 20; j++) sTop[j * 256 + tid] = TOP_SENTINEL;
    float kthf = -FLT_MAX;
    int kpos = 0;

    // ---- prefetch B tile 0 into registers ----
    uint4 pre[12];
    float spre = 0.f;
#pragma unroll
    for (int i = 0; i < 12; i++) {
        int u = tid + 256 * i;
        int row = u / 24, c = u % 24;
        int so = ((c >= 16) ? 128 : 0) + (c & 7) * 16;
        pre[i] = *reinterpret_cast<const uint4*>(xsrc + (size_t)(bbase + row) * 256 + so);
    }
    if (tid < 128) spre = g_sq[bbase + tid];
    __syncthreads();

    uint32_t sbase = smem_u32(sm);
    uint32_t aab = sbase + OFF_A + (w * 16 + (lane & 15)) * 400 + (lane >> 4) * 16;
    uint32_t bab = sbase + OFF_B + ((lane & 7) + ((lane >> 4) << 3)) * 400 + (((lane >> 3) & 1) * 16);
    float* Drow_sc = reinterpret_cast<float*>(sm + OFF_D + w * 8320 + (lane >> 1) * 520);
    float* Dst = reinterpret_cast<float*>(sm + OFF_D + w * 8320);
    float* nsq = reinterpret_cast<float*>(sm + OFF_NSQ);
    int half = lane & 1;

#pragma unroll 1
    for (int t = 0; t < 32; t++) {
        int mt = t * 128;
        // STS prefetched B tile + nsq
#pragma unroll
        for (int i = 0; i < 12; i++) {
            int u = tid + 256 * i;
            int row = u / 24, c = u % 24;
            *reinterpret_cast<uint4*>(sm + OFF_B + row * 400 + (c >> 3) * 128 + (c & 7) * 16) = pre[i];
        }
        if (tid < 128) nsq[tid] = -spre;
        __syncthreads();

        // prefetch next tile
        if (t < 31) {
            int nmt = mt + 128;
#pragma unroll
            for (int i = 0; i < 12; i++) {
                int u = tid + 256 * i;
                int row = u / 24, c = u % 24;
                int so = ((c >= 16) ? 128 : 0) + (c & 7) * 16;
                pre[i] = *reinterpret_cast<const uint4*>(xsrc + (size_t)(bbase + nmt + row) * 256 + so);
            }
            if (tid < 128) spre = g_sq[bbase + nmt + tid];
        }

        // ---- MMA: 16 rows x 128 cols, K=192 ----
        float cacc[16][4];
#pragma unroll
        for (int n = 0; n < 16; n++)
#pragma unroll
            for (int j = 0; j < 4; j++) cacc[n][j] = 0.f;
#pragma unroll
        for (int s = 0; s < 12; s++) {
            uint32_t afr[4];
            ldsm4(afr, aab + s * 32);
#pragma unroll
            for (int t2 = 0; t2 < 8; t2++) {
                uint32_t bfr[4];
                ldsm4(bfr, bab + t2 * 6400 + s * 32);
                mma_bf16(cacc[2 * t2], afr, bfr);
                mma_bf16(cacc[2 * t2 + 1], afr, bfr + 2);
            }
        }
        // ---- store D tile (warp-private) ----
        {
            int rlo = lane >> 2;
#pragma unroll
            for (int n = 0; n < 16; n++) {
                int col = n * 8 + (lane & 3) * 2;
                *reinterpret_cast<float2*>(Dst + rlo * 130 + col) = make_float2(cacc[n][0], cacc[n][1]);
                *reinterpret_cast<float2*>(Dst + (rlo + 8) * 130 + col) = make_float2(cacc[n][2], cacc[n][3]);
            }
        }
        __syncwarp();

        // ---- scan: lane owns row lane>>1, cols half*64..+63 ----
        ull pend = 0;
        int cb = half * 64;
#pragma unroll
        for (int i = 0; i < 32; i++) {
            float2 d = *reinterpret_cast<const float2*>(Drow_sc + cb + 2 * i);
            float k0 = fmaf(2.f, d.x, nsq[cb + 2 * i]);
            float k1 = fmaf(2.f, d.y, nsq[cb + 2 * i + 1]);
            if (k0 > kthf) pend |= (1ull << (2 * i));
            if (k1 > kthf) pend |= (1ull << (2 * i + 1));
        }
        while (__any_sync(0xffffffffu, pend != 0ull)) {
            if (pend) {
                int slot = __ffsll(pend) - 1;
                pend &= pend - 1;
                int col = cb + slot;
                float key = fmaf(2.f, Drow_sc[col], nsq[col]);
                if (key > kthf) {
                    uint32_t u = __float_as_uint(key);
                    uint32_t okey = (u & 0x80000000u) ? ~u : (u | 0x80000000u);
                    ull packed = ((ull)okey << 32) | (uint32_t)(~(uint32_t)(mt + col));
                    sTop[kpos * 256 + tid] = packed;
                    ull mn = sTop[tid]; int mp = 0;
#pragma unroll
                    for (int j = 1; j < 20; j++) {
                        ull v = sTop[j * 256 + tid];
                        if (v < mn) { mn = v; mp = j; }
                    }
                    kpos = mp;
                    uint32_t hi = (uint32_t)(mn >> 32);
                    uint32_t u2 = (hi & 0x80000000u) ? (hi ^ 0x80000000u) : ~hi;
                    kthf = __uint_as_float(u2);
                }
            }
        }
        __syncthreads();
    }

    // ---- merge: even lane merges its list with odd neighbor's (same row) ----
    __syncwarp();
    if (!(lane & 1)) {
        int row_pt = bbase + r0 + w * 16 + (lane >> 1);
        int* op = g_idx + (size_t)row_pt * KK;
#pragma unroll 1
        for (int j = 0; j < KK; j++) {
            ull best = 0; int bp = 0;
#pragma unroll 1
            for (int q = 0; q < 40; q++) {
                ull v = sTop[(q >> 1) * 256 + tid + (q & 1)];
                if (v > best) { best = v; bp = q; }
            }
            op[j] = (int)(~(uint32_t)best);
            sTop[(bp >> 1) * 256 + tid + (bp & 1)] = 0;
        }
    }
}

// ---------------- D: gather p[idx]+q, max/min over k, BN partial sums ----------------
__global__ void k_gather() {
    int tid = threadIdx.x;  // 256
    int g = tid >> 6, o = tid & 63;
    float psum = 0.f, psq = 0.f;
#pragma unroll 1
    for (int i = 0; i < 8; i++) {
        int point = blockIdx.x * 32 + i * 4 + g;
        int b = point >> 12;
        const int* ix = g_idx + (size_t)point * KK;
        float qv = g_q[(size_t)point * OO + o];
        const float* pb = g_p + (((size_t)b) << 12) * OO;
        float mx = -FLT_MAX, mn = FLT_MAX;
#pragma unroll
        for (int k = 0; k < KK; k++) {
            int j = ix[k];
            float y = pb[(size_t)j * OO + o] + qv;
            mx = fmaxf(mx, y);
            mn = fminf(mn, y);
            psum += y;
            psq = fmaf(y, y, psq);
        }
        g_ymax[(size_t)point * OO + o] = mx;
        g_ymin[(size_t)point * OO + o] = mn;
    }
    __shared__ float ss[256], s2[256];
    ss[tid] = psum; s2[tid] = psq;
    __syncthreads();
    if (tid < 64) {
        float a = ss[tid] + ss[tid + 64] + ss[tid + 128] + ss[tid + 192];
        float c = s2[tid] + s2[tid + 64] + s2[tid + 128] + s2[tid + 192];
        g_part[(size_t)blockIdx.x * 128 + tid] = a;
        g_part[(size_t)blockIdx.x * 128 + 64 + tid] = c;
    }
}

__global__ void k_reduce() {
    int i = blockIdx.x;
    int t = threadIdx.x;
    float s = 0.f;
    for (int blk = t; blk < DBLK; blk += 256) s += g_part[(size_t)blk * 128 + i];
    __shared__ float smr[256];
    smr[t] = s;
    __syncthreads();
    for (int wd = 128; wd > 0; wd >>= 1) {
        if (t < wd) smr[t] += smr[t + wd];
        __syncthreads();
    }
    if (t == 0) g_stats[i] = smr[0];
}

__global__ void k_out(const float* __restrict__ gamma, const float* __restrict__ beta,
                      float* __restrict__ out) {
    __shared__ float smT[OO][33];
    int b = blockIdx.y, n0 = blockIdx.x * 32;
    int tid = threadIdx.x;
    const float CNTf = (float)(BB * NN * KK);
#pragma unroll 1
    for (int i = tid; i < 32 * OO; i += 256) {
        int n = i >> 6, o = i & 63;
        float s = g_stats[o], s2v = g_stats[64 + o];
        float mean = s / CNTf;
        float var = s2v / CNTf - mean * mean;
        float rstd = rsqrtf(var + EPS);
        float gm = gamma[o];
        size_t yi = ((size_t)b * NN + n0 + n) * OO + o;
        float v = (gm >= 0.f) ? g_ymax[yi] : g_ymin[yi];
        float z = gm * (v - mean) * rstd + beta[o];
        z = (z >= 0.f) ? z : NEG_SLOPE * z;
        smT[o][n] = z;
    }
    __syncthreads();
#pragma unroll 1
    for (int i = tid; i < OO * 32; i += 256) {
        int o = i >> 5, n = i & 31;
        out[((size_t)b * OO + o) * NN + n0 + n] = smT[o][n];
    }
}

extern "C" void kernel_launch(void* const* d_in, const int* in_sizes, int n_in,
                              void* d_out, int out_size) {
    const float* inp = (const float*)d_in[0];
    const float* W = (const float*)d_in[1];
    const float* gamma = (const float*)d_in[2];
    const float* beta = (const float*)d_in[3];
    float* out = (float*)d_out;

    cudaFuncSetAttribute(k_knn_wmma, cudaFuncAttributeMaxDynamicSharedMemorySize, DYN_BYTES);

    k_transpose<<<dim3(NN / 32, CC / 32, BB), dim3(32, 8)>>>(inp);
    k_split<<<BB * NN * 4 / 256, 256>>>();
    k_pq<<<BB * NN / 128, 128>>>(W);
    k_knn_wmma<<<dim3(NN / 128, BB), 256, DYN_BYTES>>>();
    k_gather<<<DBLK, 256>>>();
    k_reduce<<<2 * OO, 256>>>();
    k_out<<<dim3(NN / 32, BB), 256>>>(gamma, beta, out);
}

// round 6
// speedup vs baseline: 1.8895x; 1.1270x over previous
#include <cuda_runtime.h>
#include <cuda_bf16.h>
#include <float.h>
#include <cstdint>

#define BB 8
#define NN 4096
#define CC 64
#define OO 64
#define KK 20
#define NEG_SLOPE 0.2f
#define EPS 1e-5f
#define DBLK 1024

typedef unsigned long long ull;

// sentinel: packed(-FLT_MAX key, idx decode 0)
#define TOP_SENTINEL 0x00800000FFFFFFFFull

// ---------------- smem map for k_knn_wmma ----------------
// A: 128 x 272B ([hi|lo] bf16, 16B pad)      -> 34816
// B: 128 x 272B                              -> 34816
// D: 8 warps x 32 rows x 66 floats (264B)    -> 67584
// TOP: SoA 20 slots x 256 threads x 8B       -> 40960
// SSQ: 128 x 4B
#define OFF_A   0
#define OFF_B   34816
#define OFF_D   69632
#define OFF_TOP 137216
#define OFF_SSQ 178176
#define DYN_BYTES 178688

__device__ __forceinline__ uint32_t smem_u32(const void* p) {
    uint32_t a;
    asm("{ .reg .u64 t; cvta.to.shared.u64 t, %1; cvt.u32.u64 %0, t; }" : "=r"(a) : "l"(p));
    return a;
}
__device__ __forceinline__ void ldsm4(uint32_t* r, uint32_t addr) {
    asm volatile("ldmatrix.sync.aligned.m8n8.x4.shared.b16 {%0,%1,%2,%3}, [%4];"
        : "=r"(r[0]), "=r"(r[1]), "=r"(r[2]), "=r"(r[3]) : "r"(addr));
}
__device__ __forceinline__ void mma_bf16(float* c, const uint32_t* a, const uint32_t* b) {
    asm volatile(
        "mma.sync.aligned.m16n8k16.row.col.f32.bf16.bf16.f32 "
        "{%0,%1,%2,%3}, {%4,%5,%6,%7}, {%8,%9}, {%0,%1,%2,%3};"
        : "+f"(c[0]), "+f"(c[1]), "+f"(c[2]), "+f"(c[3])
        : "r"(a[0]), "r"(a[1]), "r"(a[2]), "r"(a[3]), "r"(b[0]), "r"(b[1]));
}

// ---------------- scratch ----------------
__device__ __align__(16) float g_xT[BB * NN * CC];
__device__ __align__(16) __nv_bfloat16 g_xs[BB * NN * 128];  // [hi(64)|lo(64)] per point
__device__ float g_sq[BB * NN];
__device__ __align__(16) float g_p[BB * NN * OO];
__device__ __align__(16) float g_q[BB * NN * OO];
__device__ int   g_idx[BB * NN * KK];
__device__ __align__(16) float g_ymax[BB * NN * OO];
__device__ __align__(16) float g_ymin[BB * NN * OO];
__device__ float g_part[DBLK * 2 * OO];
__device__ float g_stats[2 * OO];

// ---------------- A1: transpose (B,C,N) -> (B,N,C) ----------------
__global__ void k_transpose(const float* __restrict__ in) {
    __shared__ float t[32][33];
    int b = blockIdx.z, c0 = blockIdx.y * 32, n0 = blockIdx.x * 32;
    int tx = threadIdx.x, ty = threadIdx.y;
#pragma unroll
    for (int j = 0; j < 4; j++)
        t[ty + 8 * j][tx] = in[((size_t)b * CC + (c0 + ty + 8 * j)) * NN + n0 + tx];
    __syncthreads();
#pragma unroll
    for (int j = 0; j < 4; j++)
        g_xT[((size_t)b * NN + (n0 + ty + 8 * j)) * CC + c0 + tx] = t[tx][ty + 8 * j];
}

// ---------------- A1b: split fp32 -> bf16 hi/lo ----------------
__global__ void k_split() {
    int idx = blockIdx.x * 256 + threadIdx.x;
    int point = idx >> 2, part = idx & 3;
    const float4* src = reinterpret_cast<const float4*>(g_xT + (size_t)point * CC + part * 16);
    union { __nv_bfloat162 h2[8]; uint4 v[2]; } hi, lo;
#pragma unroll
    for (int j = 0; j < 4; j++) {
        float4 v = src[j];
        float f[4] = {v.x, v.y, v.z, v.w};
#pragma unroll
        for (int e = 0; e < 2; e++) {
            float a = f[2 * e], b2 = f[2 * e + 1];
            __nv_bfloat16 ha = __float2bfloat16_rn(a);
            __nv_bfloat16 hb = __float2bfloat16_rn(b2);
            __nv_bfloat16 la = __float2bfloat16_rn(a - __bfloat162float(ha));
            __nv_bfloat16 lb = __float2bfloat16_rn(b2 - __bfloat162float(hb));
            hi.h2[2 * j + e] = __nv_bfloat162(ha, hb);
            lo.h2[2 * j + e] = __nv_bfloat162(la, lb);
        }
    }
    uint4* dhi = reinterpret_cast<uint4*>(g_xs + (size_t)point * 128 + part * 16);
    uint4* dlo = reinterpret_cast<uint4*>(g_xs + (size_t)point * 128 + 64 + part * 16);
    dhi[0] = hi.v[0]; dhi[1] = hi.v[1];
    dlo[0] = lo.v[0]; dlo[1] = lo.v[1];
}

// ---------------- A2: squared norms + p,q projections ----------------
__global__ void k_pq(const float* __restrict__ W) {
    __shared__ float sWp[OO][CC];
    __shared__ float sWd[OO][CC];
    int tid = threadIdx.x;
    for (int i = tid; i < OO * CC; i += 128) {
        int o = i >> 6, c = i & 63;
        float wp = W[o * 2 * CC + c];
        sWp[o][c] = wp;
        sWd[o][c] = W[o * 2 * CC + CC + c] - wp;
    }
    __syncthreads();
    int point = blockIdx.x * 128 + tid;
    const float4* xr4 = reinterpret_cast<const float4*>(g_xT + (size_t)point * CC);
    float xr[CC];
    float sq = 0.f;
#pragma unroll
    for (int i = 0; i < 16; i++) {
        float4 v = xr4[i];
        xr[4 * i] = v.x; xr[4 * i + 1] = v.y; xr[4 * i + 2] = v.z; xr[4 * i + 3] = v.w;
        sq = fmaf(v.x, v.x, sq); sq = fmaf(v.y, v.y, sq);
        sq = fmaf(v.z, v.z, sq); sq = fmaf(v.w, v.w, sq);
    }
    g_sq[point] = sq;
    float* pp = g_p + (size_t)point * OO;
    float* qq = g_q + (size_t)point * OO;
#pragma unroll 1
    for (int o = 0; o < OO; o++) {
        const float4* wp4 = reinterpret_cast<const float4*>(&sWp[o][0]);
        const float4* wd4 = reinterpret_cast<const float4*>(&sWd[o][0]);
        float ap = 0.f, aq = 0.f;
#pragma unroll
        for (int i = 0; i < 16; i++) {
            float4 wp = wp4[i], wd = wd4[i];
            ap = fmaf(xr[4 * i], wp.x, ap); ap = fmaf(xr[4 * i + 1], wp.y, ap);
            ap = fmaf(xr[4 * i + 2], wp.z, ap); ap = fmaf(xr[4 * i + 3], wp.w, ap);
            aq = fmaf(xr[4 * i], wd.x, aq); aq = fmaf(xr[4 * i + 1], wd.y, aq);
            aq = fmaf(xr[4 * i + 2], wd.z, aq); aq = fmaf(xr[4 * i + 3], wd.w, aq);
        }
        pp[o] = ap;
        qq[o] = aq;
    }
}

// ===================== B: HMMA distance GEMM + per-lane top-20 =====================
// K=192 virtual k-steps over deduped [hi|lo] smem: A steps {hi0-3, lo0-3, hi0-3},
// B steps {hi0-3, hi0-3, lo0-3}  =>  acc = hi·hi + lo·hi + hi·lo ≈ fp32 dot.
// Accumulator initialized with -||x_m||^2/2: final acc D' = dot - sq/2 (= key/2, monotone).
__global__ void __launch_bounds__(256, 1) k_knn_wmma() {
    extern __shared__ __align__(16) char sm[];
    int tid = threadIdx.x;
    int w = tid >> 5, lane = tid & 31;
    int rg = w >> 1, cg = w & 1;       // warp = 32 rows (rg) x 64 cols (cg)
    int b = blockIdx.y, r0 = blockIdx.x * 128, bbase = b * NN;
    const char* xsrc = (const char*)g_xs;

    // ---- A tile (resident): straight copy of [hi|lo] rows, 272B stride ----
#pragma unroll
    for (int i = 0; i < 8; i++) {
        int u = tid + 256 * i;
        int row = u >> 4, c = u & 15;
        uint4 v = *reinterpret_cast<const uint4*>(xsrc + (size_t)(bbase + r0 + row) * 256 + c * 16);
        *reinterpret_cast<uint4*>(sm + OFF_A + row * 272 + c * 16) = v;
    }

    // ---- top-20 state (SoA) ----
    ull* sTop = reinterpret_cast<ull*>(sm + OFF_TOP);
#pragma unroll
    for (int j = 0; j < 20; j++) sTop[j * 256 + tid] = TOP_SENTINEL;
    float kthd = -FLT_MAX;   // threshold in D' domain
    int kpos = 0;

    // ---- prefetch B tile 0 ----
    uint4 pre[8];
    float spre = 0.f;
#pragma unroll
    for (int i = 0; i < 8; i++) {
        int u = tid + 256 * i;
        int row = u >> 4, c = u & 15;
        pre[i] = *reinterpret_cast<const uint4*>(xsrc + (size_t)(bbase + row) * 256 + c * 16);
    }
    if (tid < 128) spre = g_sq[bbase + tid];
    __syncthreads();

    uint32_t sbase = smem_u32(sm);
    // A ldsm base per row-subblock i (i=0,1): rows rg*32 + i*16
    uint32_t aab0 = sbase + OFF_A + (rg * 32 + (lane & 15)) * 272 + (lane >> 4) * 16;
    uint32_t aab1 = aab0 + 16 * 272;
    // B ldsm base: col block t2 adds t2*16 rows
    uint32_t bab = sbase + OFF_B + (cg * 64 + (lane & 7) + ((lane >> 4) << 3)) * 272 +
                   (((lane >> 3) & 1) * 16);
    float* Dwarp = reinterpret_cast<float*>(sm + OFF_D + w * 8448);   // 32 x 66 floats
    float* Drow = Dwarp + lane * 66;
    float* ssq = reinterpret_cast<float*>(sm + OFF_SSQ);
    const float2* ssq2h = reinterpret_cast<const float2*>(ssq) + cg * 32;

    // virtual k-step byte offsets into [hi(128B)|lo(128B)] rows
    const int aoff[12] = {0,32,64,96, 128,160,192,224, 0,32,64,96};
    const int boff[12] = {0,32,64,96, 0,32,64,96, 128,160,192,224};

#pragma unroll 1
    for (int t = 0; t < 32; t++) {
        int mt = t * 128;
        // STS prefetched B tile + sq
#pragma unroll
        for (int i = 0; i < 8; i++) {
            int u = tid + 256 * i;
            int row = u >> 4, c = u & 15;
            *reinterpret_cast<uint4*>(sm + OFF_B + row * 272 + c * 16) = pre[i];
        }
        if (tid < 128) ssq[tid] = spre;
        __syncthreads();

        // prefetch next tile
        if (t < 31) {
            int nmt = mt + 128;
#pragma unroll
            for (int i = 0; i < 8; i++) {
                int u = tid + 256 * i;
                int row = u >> 4, c = u & 15;
                pre[i] = *reinterpret_cast<const uint4*>(xsrc + (size_t)(bbase + nmt + row) * 256 + c * 16);
            }
            if (tid < 128) spre = g_sq[bbase + nmt + tid];
        }

        // ---- accumulator init with -sq/2 (folds distance term into GEMM) ----
        float cacc[2][4][2][4];
#pragma unroll
        for (int t2 = 0; t2 < 4; t2++)
#pragma unroll
            for (int h = 0; h < 2; h++) {
                float2 sv = ssq2h[t2 * 8 + h * 4 + (lane & 3)];
                float v0 = -0.5f * sv.x, v1 = -0.5f * sv.y;
#pragma unroll
                for (int i = 0; i < 2; i++) {
                    cacc[i][t2][h][0] = v0; cacc[i][t2][h][1] = v1;
                    cacc[i][t2][h][2] = v0; cacc[i][t2][h][3] = v1;
                }
            }

        // ---- MMA: 32 rows x 64 cols, 12 virtual k-steps ----
#pragma unroll
        for (int s = 0; s < 12; s++) {
            uint32_t afr0[4], afr1[4];
            ldsm4(afr0, aab0 + aoff[s]);
            ldsm4(afr1, aab1 + aoff[s]);
#pragma unroll
            for (int t2 = 0; t2 < 4; t2++) {
                uint32_t bfr[4];
                ldsm4(bfr, bab + t2 * 4352 + boff[s]);
                mma_bf16(cacc[0][t2][0], afr0, bfr);
                mma_bf16(cacc[0][t2][1], afr0, bfr + 2);
                mma_bf16(cacc[1][t2][0], afr1, bfr);
                mma_bf16(cacc[1][t2][1], afr1, bfr + 2);
            }
        }
        // ---- store D tile (warp-private, rows local 0..31) ----
        {
            int rl = lane >> 2, cl = (lane & 3) * 2;
#pragma unroll
            for (int i = 0; i < 2; i++)
#pragma unroll
                for (int t2 = 0; t2 < 4; t2++)
#pragma unroll
                    for (int h = 0; h < 2; h++) {
                        int col = t2 * 16 + h * 8 + cl;
                        float* base = Dwarp + (i * 16 + rl) * 66 + col;
                        *reinterpret_cast<float2*>(base) =
                            make_float2(cacc[i][t2][h][0], cacc[i][t2][h][1]);
                        *reinterpret_cast<float2*>(base + 8 * 66) =
                            make_float2(cacc[i][t2][h][2], cacc[i][t2][h][3]);
                    }
        }
        __syncwarp();

        // ---- scan: lane owns local row `lane` (64 cols) ----
        ull pend = 0;
#pragma unroll
        for (int i = 0; i < 32; i++) {
            float2 d = *reinterpret_cast<const float2*>(Drow + 2 * i);
            if (d.x > kthd) pend |= (1ull << (2 * i));
            if (d.y > kthd) pend |= (1ull << (2 * i + 1));
        }
        while (__any_sync(0xffffffffu, pend != 0ull)) {
            if (pend) {
                int slot = __ffsll(pend) - 1;
                pend &= pend - 1;
                float key = Drow[slot];
                if (key > kthd) {
                    int idx = mt + cg * 64 + slot;
                    uint32_t u = __float_as_uint(key);
                    uint32_t okey = (u & 0x80000000u) ? ~u : (u | 0x80000000u);
                    ull packed = ((ull)okey << 32) | (uint32_t)(~(uint32_t)idx);
                    sTop[kpos * 256 + tid] = packed;
                    ull mn = sTop[tid]; int mp = 0;
#pragma unroll
                    for (int j = 1; j < 20; j++) {
                        ull v = sTop[j * 256 + tid];
                        if (v < mn) { mn = v; mp = j; }
                    }
                    kpos = mp;
                    uint32_t hi = (uint32_t)(mn >> 32);
                    uint32_t u2 = (hi & 0x80000000u) ? (hi ^ 0x80000000u) : ~hi;
                    kthd = __uint_as_float(u2);
                }
            }
        }
        __syncthreads();
    }

    // ---- merge: cg==0 warps merge own list with partner (tid+32, cg==1) ----
    if (cg == 0) {
        int row_pt = bbase + r0 + rg * 32 + lane;
        int* op = g_idx + (size_t)row_pt * KK;
#pragma unroll 1
        for (int j = 0; j < KK; j++) {
            ull best = 0; int bp = 0;
#pragma unroll 1
            for (int q = 0; q < 40; q++) {
                ull v = (q < 20) ? sTop[q * 256 + tid] : sTop[(q - 20) * 256 + tid + 32];
                if (v > best) { best = v; bp = q; }
            }
            op[j] = (int)(~(uint32_t)best);
            if (bp < 20) sTop[bp * 256 + tid] = 0;
            else sTop[(bp - 20) * 256 + tid + 32] = 0;
        }
    }
}

// ---------------- D: gather p[idx]+q, max/min over k, BN partial sums ----------------
__global__ void k_gather() {
    int tid = threadIdx.x;  // 256
    int g = tid >> 6, o = tid & 63;
    float psum = 0.f, psq = 0.f;
#pragma unroll 1
    for (int i = 0; i < 8; i++) {
        int point = blockIdx.x * 32 + i * 4 + g;
        int b = point >> 12;
        const int* ix = g_idx + (size_t)point * KK;
        float qv = g_q[(size_t)point * OO + o];
        const float* pb = g_p + (((size_t)b) << 12) * OO;
        float mx = -FLT_MAX, mn = FLT_MAX;
#pragma unroll
        for (int k = 0; k < KK; k++) {
            int j = ix[k];
            float y = pb[(size_t)j * OO + o] + qv;
            mx = fmaxf(mx, y);
            mn = fminf(mn, y);
            psum += y;
            psq = fmaf(y, y, psq);
        }
        g_ymax[(size_t)point * OO + o] = mx;
        g_ymin[(size_t)point * OO + o] = mn;
    }
    __shared__ float ss[256], s2[256];
    ss[tid] = psum; s2[tid] = psq;
    __syncthreads();
    if (tid < 64) {
        float a = ss[tid] + ss[tid + 64] + ss[tid + 128] + ss[tid + 192];
        float c = s2[tid] + s2[tid + 64] + s2[tid + 128] + s2[tid + 192];
        g_part[(size_t)blockIdx.x * 128 + tid] = a;
        g_part[(size_t)blockIdx.x * 128 + 64 + tid] = c;
    }
}

__global__ void k_reduce() {
    int i = blockIdx.x;
    int t = threadIdx.x;
    float s = 0.f;
    for (int blk = t; blk < DBLK; blk += 256) s += g_part[(size_t)blk * 128 + i];
    __shared__ float smr[256];
    smr[t] = s;
    __syncthreads();
    for (int wd = 128; wd > 0; wd >>= 1) {
        if (t < wd) smr[t] += smr[t + wd];
        __syncthreads();
    }
    if (t == 0) g_stats[i] = smr[0];
}

__global__ void k_out(const float* __restrict__ gamma, const float* __restrict__ beta,
                      float* __restrict__ out) {
    __shared__ float smT[OO][33];
    int b = blockIdx.y, n0 = blockIdx.x * 32;
    int tid = threadIdx.x;
    const float CNTf = (float)(BB * NN * KK);
#pragma unroll 1
    for (int i = tid; i < 32 * OO; i += 256) {
        int n = i >> 6, o = i & 63;
        float s = g_stats[o], s2v = g_stats[64 + o];
        float mean = s / CNTf;
        float var = s2v / CNTf - mean * mean;
        float rstd = rsqrtf(var + EPS);
        float gm = gamma[o];
        size_t yi = ((size_t)b * NN + n0 + n) * OO + o;
        float v = (gm >= 0.f) ? g_ymax[yi] : g_ymin[yi];
        float z = gm * (v - mean) * rstd + beta[o];
        z = (z >= 0.f) ? z : NEG_SLOPE * z;
        smT[o][n] = z;
    }
    __syncthreads();
#pragma unroll 1
    for (int i = tid; i < OO * 32; i += 256) {
        int o = i >> 5, n = i & 31;
        out[((size_t)b * OO + o) * NN + n0 + n] = smT[o][n];
    }
}

extern "C" void kernel_launch(void* const* d_in, const int* in_sizes, int n_in,
                              void* d_out, int out_size) {
    const float* inp = (const float*)d_in[0];
    const float* W = (const float*)d_in[1];
    const float* gamma = (const float*)d_in[2];
    const float* beta = (const float*)d_in[3];
    float* out = (float*)d_out;

    cudaFuncSetAttribute(k_knn_wmma, cudaFuncAttributeMaxDynamicSharedMemorySize, DYN_BYTES);

    k_transpose<<<dim3(NN / 32, CC / 32, BB), dim3(32, 8)>>>(inp);
    k_split<<<BB * NN * 4 / 256, 256>>>();
    k_pq<<<BB * NN / 128, 128>>>(W);
    k_knn_wmma<<<dim3(NN / 128, BB), 256, DYN_BYTES>>>();
    k_gather<<<DBLK, 256>>>();
    k_reduce<<<2 * OO, 256>>>();
    k_out<<<dim3(NN / 32, BB), 256>>>(gamma, beta, out);
}

// round 7
// speedup vs baseline: 1.9334x; 1.0232x over previous
#include <cuda_runtime.h>
#include <cuda_bf16.h>
#include <float.h>
#include <cstdint>

#define BB 8
#define NN 4096
#define CC 64
#define OO 64
#define KK 20
#define NEG_SLOPE 0.2f
#define EPS 1e-5f
#define DBLK 1024

typedef unsigned long long ull;

// sentinel: packed(-FLT_MAX key, idx decode 0)
#define TOP_SENTINEL 0x00800000FFFFFFFFull

// ---------------- smem map for k_knn_wmma (128-thread CTA, 64 queries) ----------------
// A: 64 x 272B ([hi|lo] bf16 + 16B pad)      -> 17408
// B: 128 x 272B                              -> 34816
// D: 4 warps x 32 rows x 66 floats (264B)    -> 33792
// TOP: SoA 20 slots x 128 threads x 8B       -> 20480
// SSQ: 128 x 4B                              -> 512
#define OFF_A   0
#define OFF_B   17408
#define OFF_D   52224
#define OFF_TOP 86016
#define OFF_SSQ 106496
#define DYN_BYTES 107008

__device__ __forceinline__ uint32_t smem_u32(const void* p) {
    uint32_t a;
    asm("{ .reg .u64 t; cvta.to.shared.u64 t, %1; cvt.u32.u64 %0, t; }" : "=r"(a) : "l"(p));
    return a;
}
__device__ __forceinline__ void ldsm4(uint32_t* r, uint32_t addr) {
    asm volatile("ldmatrix.sync.aligned.m8n8.x4.shared.b16 {%0,%1,%2,%3}, [%4];"
        : "=r"(r[0]), "=r"(r[1]), "=r"(r[2]), "=r"(r[3]) : "r"(addr));
}
__device__ __forceinline__ void mma_bf16(float* c, const uint32_t* a, const uint32_t* b) {
    asm volatile(
        "mma.sync.aligned.m16n8k16.row.col.f32.bf16.bf16.f32 "
        "{%0,%1,%2,%3}, {%4,%5,%6,%7}, {%8,%9}, {%0,%1,%2,%3};"
        : "+f"(c[0]), "+f"(c[1]), "+f"(c[2]), "+f"(c[3])
        : "r"(a[0]), "r"(a[1]), "r"(a[2]), "r"(a[3]), "r"(b[0]), "r"(b[1]));
}
#define CP_ASYNC16(sa, gp) \
    asm volatile("cp.async.cg.shared.global [%0], [%1], 16;" :: "r"(sa), "l"(gp))
#define CP_ASYNC4(sa, gp) \
    asm volatile("cp.async.ca.shared.global [%0], [%1], 4;" :: "r"(sa), "l"(gp))
#define CP_COMMIT() asm volatile("cp.async.commit_group;" ::: "memory")
#define CP_WAIT0()  asm volatile("cp.async.wait_group 0;" ::: "memory")

// ---------------- scratch ----------------
__device__ __align__(16) float g_xT[BB * NN * CC];
__device__ __align__(16) __nv_bfloat16 g_xs[BB * NN * 128];  // [hi(64)|lo(64)] per point
__device__ float g_sq[BB * NN];
__device__ __align__(16) float g_p[BB * NN * OO];
__device__ __align__(16) float g_q[BB * NN * OO];
__device__ int   g_idx[BB * NN * KK];
__device__ __align__(16) float g_ymax[BB * NN * OO];
__device__ __align__(16) float g_ymin[BB * NN * OO];
__device__ float g_part[DBLK * 2 * OO];
__device__ float g_stats[2 * OO];

// ---------------- A1: transpose (B,C,N) -> (B,N,C) ----------------
__global__ void k_transpose(const float* __restrict__ in) {
    __shared__ float t[32][33];
    int b = blockIdx.z, c0 = blockIdx.y * 32, n0 = blockIdx.x * 32;
    int tx = threadIdx.x, ty = threadIdx.y;
#pragma unroll
    for (int j = 0; j < 4; j++)
        t[ty + 8 * j][tx] = in[((size_t)b * CC + (c0 + ty + 8 * j)) * NN + n0 + tx];
    __syncthreads();
#pragma unroll
    for (int j = 0; j < 4; j++)
        g_xT[((size_t)b * NN + (n0 + ty + 8 * j)) * CC + c0 + tx] = t[tx][ty + 8 * j];
}

// ---------------- A1b: split fp32 -> bf16 hi/lo ----------------
__global__ void k_split() {
    int idx = blockIdx.x * 256 + threadIdx.x;
    int point = idx >> 2, part = idx & 3;
    const float4* src = reinterpret_cast<const float4*>(g_xT + (size_t)point * CC + part * 16);
    union { __nv_bfloat162 h2[8]; uint4 v[2]; } hi, lo;
#pragma unroll
    for (int j = 0; j < 4; j++) {
        float4 v = src[j];
        float f[4] = {v.x, v.y, v.z, v.w};
#pragma unroll
        for (int e = 0; e < 2; e++) {
            float a = f[2 * e], b2 = f[2 * e + 1];
            __nv_bfloat16 ha = __float2bfloat16_rn(a);
            __nv_bfloat16 hb = __float2bfloat16_rn(b2);
            __nv_bfloat16 la = __float2bfloat16_rn(a - __bfloat162float(ha));
            __nv_bfloat16 lb = __float2bfloat16_rn(b2 - __bfloat162float(hb));
            hi.h2[2 * j + e] = __nv_bfloat162(ha, hb);
            lo.h2[2 * j + e] = __nv_bfloat162(la, lb);
        }
    }
    uint4* dhi = reinterpret_cast<uint4*>(g_xs + (size_t)point * 128 + part * 16);
    uint4* dlo = reinterpret_cast<uint4*>(g_xs + (size_t)point * 128 + 64 + part * 16);
    dhi[0] = hi.v[0]; dhi[1] = hi.v[1];
    dlo[0] = lo.v[0]; dlo[1] = lo.v[1];
}

// ---------------- A2: squared norms + p,q projections ----------------
__global__ void k_pq(const float* __restrict__ W) {
    __shared__ float sWp[OO][CC];
    __shared__ float sWd[OO][CC];
    int tid = threadIdx.x;
    for (int i = tid; i < OO * CC; i += 128) {
        int o = i >> 6, c = i & 63;
        float wp = W[o * 2 * CC + c];
        sWp[o][c] = wp;
        sWd[o][c] = W[o * 2 * CC + CC + c] - wp;
    }
    __syncthreads();
    int point = blockIdx.x * 128 + tid;
    const float4* xr4 = reinterpret_cast<const float4*>(g_xT + (size_t)point * CC);
    float xr[CC];
    float sq = 0.f;
#pragma unroll
    for (int i = 0; i < 16; i++) {
        float4 v = xr4[i];
        xr[4 * i] = v.x; xr[4 * i + 1] = v.y; xr[4 * i + 2] = v.z; xr[4 * i + 3] = v.w;
        sq = fmaf(v.x, v.x, sq); sq = fmaf(v.y, v.y, sq);
        sq = fmaf(v.z, v.z, sq); sq = fmaf(v.w, v.w, sq);
    }
    g_sq[point] = sq;
    float* pp = g_p + (size_t)point * OO;
    float* qq = g_q + (size_t)point * OO;
#pragma unroll 1
    for (int o = 0; o < OO; o++) {
        const float4* wp4 = reinterpret_cast<const float4*>(&sWp[o][0]);
        const float4* wd4 = reinterpret_cast<const float4*>(&sWd[o][0]);
        float ap = 0.f, aq = 0.f;
#pragma unroll
        for (int i = 0; i < 16; i++) {
            float4 wp = wp4[i], wd = wd4[i];
            ap = fmaf(xr[4 * i], wp.x, ap); ap = fmaf(xr[4 * i + 1], wp.y, ap);
            ap = fmaf(xr[4 * i + 2], wp.z, ap); ap = fmaf(xr[4 * i + 3], wp.w, ap);
            aq = fmaf(xr[4 * i], wd.x, aq); aq = fmaf(xr[4 * i + 1], wd.y, aq);
            aq = fmaf(xr[4 * i + 2], wd.z, aq); aq = fmaf(xr[4 * i + 3], wd.w, aq);
        }
        pp[o] = ap;
        qq[o] = aq;
    }
}

// ===================== B: HMMA distance GEMM + per-lane top-20 =====================
// 128-thread CTA, 64 queries; 2 CTAs/SM. K=192 virtual k-steps over deduped [hi|lo]:
// A steps {hi,lo,hi}, B steps {hi,hi,lo} => acc = hi·hi + lo·hi + hi·lo ≈ fp32 dot.
// Accumulator init with -||x_m||^2/2: acc D' = dot - sq/2 (monotone in ref key).
__global__ void __launch_bounds__(128, 2) k_knn_wmma() {
    extern __shared__ __align__(16) char sm[];
    int tid = threadIdx.x;
    int w = tid >> 5, lane = tid & 31;
    int rg = w >> 1, cg = w & 1;       // warp = 32 rows (rg) x 64 cols (cg)
    int b = blockIdx.y, r0 = blockIdx.x * 64, bbase = b * NN;
    const char* xsrc = (const char*)g_xs;
    uint32_t sbase = smem_u32(sm);

    // ---- A tile (resident): 64 rows x 256B data, 272B stride ----
#pragma unroll
    for (int i = 0; i < 8; i++) {
        int u = tid + 128 * i;
        int row = u >> 4, c = u & 15;
        uint4 v = *reinterpret_cast<const uint4*>(xsrc + (size_t)(bbase + r0 + row) * 256 + c * 16);
        *reinterpret_cast<uint4*>(sm + OFF_A + row * 272 + c * 16) = v;
    }

    // ---- B tile 0 + ssq via cp.async ----
#pragma unroll
    for (int i = 0; i < 16; i++) {
        int u = tid + 128 * i;
        int row = u >> 4, c = u & 15;
        CP_ASYNC16(sbase + OFF_B + row * 272 + c * 16,
                   xsrc + (size_t)(bbase + row) * 256 + c * 16);
    }
    CP_ASYNC4(sbase + OFF_SSQ + tid * 4, &g_sq[bbase + tid]);
    CP_COMMIT();

    // ---- top-20 state (SoA) ----
    ull* sTop = reinterpret_cast<ull*>(sm + OFF_TOP);
#pragma unroll
    for (int j = 0; j < 20; j++) sTop[j * 128 + tid] = TOP_SENTINEL;
    float kthd = -FLT_MAX;
    int kpos = 0;

    // A ldsm base per row-subblock i (i=0,1): rows rg*32 + i*16
    uint32_t aab0 = sbase + OFF_A + (rg * 32 + (lane & 15)) * 272 + (lane >> 4) * 16;
    uint32_t aab1 = aab0 + 16 * 272;
    // B ldsm base: col block t2 adds t2*16 rows
    uint32_t bab = sbase + OFF_B + (cg * 64 + (lane & 7) + ((lane >> 4) << 3)) * 272 +
                   (((lane >> 3) & 1) * 16);
    float* Dwarp = reinterpret_cast<float*>(sm + OFF_D + w * 8448);   // 32 x 66 floats
    float* Drow = Dwarp + lane * 66;
    const float2* ssq2h = reinterpret_cast<const float2*>(sm + OFF_SSQ) + cg * 32;

    // virtual k-step byte offsets into [hi(128B)|lo(128B)] rows
    const int aoff[12] = {0,32,64,96, 128,160,192,224, 0,32,64,96};
    const int boff[12] = {0,32,64,96, 0,32,64,96, 128,160,192,224};

#pragma unroll 1
    for (int t = 0; t < 32; t++) {
        int mt = t * 128;
        CP_WAIT0();          // B tile + ssq landed (issuing thread view)
        __syncthreads();     // cross-thread visibility

        // ---- accumulator init with -sq/2 ----
        float cacc[2][4][2][4];
#pragma unroll
        for (int t2 = 0; t2 < 4; t2++)
#pragma unroll
            for (int h = 0; h < 2; h++) {
                float2 sv = ssq2h[t2 * 8 + h * 4 + (lane & 3)];
                float v0 = -0.5f * sv.x, v1 = -0.5f * sv.y;
#pragma unroll
                for (int i = 0; i < 2; i++) {
                    cacc[i][t2][h][0] = v0; cacc[i][t2][h][1] = v1;
                    cacc[i][t2][h][2] = v0; cacc[i][t2][h][3] = v1;
                }
            }

        // ---- MMA: 32 rows x 64 cols, 12 virtual k-steps ----
#pragma unroll
        for (int s = 0; s < 12; s++) {
            uint32_t afr0[4], afr1[4];
            ldsm4(afr0, aab0 + aoff[s]);
            ldsm4(afr1, aab1 + aoff[s]);
#pragma unroll
            for (int t2 = 0; t2 < 4; t2++) {
                uint32_t bfr[4];
                ldsm4(bfr, bab + t2 * 4352 + boff[s]);
                mma_bf16(cacc[0][t2][0], afr0, bfr);
                mma_bf16(cacc[0][t2][1], afr0, bfr + 2);
                mma_bf16(cacc[1][t2][0], afr1, bfr);
                mma_bf16(cacc[1][t2][1], afr1, bfr + 2);
            }
        }
        // ---- store D tile (warp-private) ----
        {
            int rl = lane >> 2, cl = (lane & 3) * 2;
#pragma unroll
            for (int i = 0; i < 2; i++)
#pragma unroll
                for (int t2 = 0; t2 < 4; t2++)
#pragma unroll
                    for (int h = 0; h < 2; h++) {
                        int col = t2 * 16 + h * 8 + cl;
                        float* base = Dwarp + (i * 16 + rl) * 66 + col;
                        *reinterpret_cast<float2*>(base) =
                            make_float2(cacc[i][t2][h][0], cacc[i][t2][h][1]);
                        *reinterpret_cast<float2*>(base + 8 * 66) =
                            make_float2(cacc[i][t2][h][2], cacc[i][t2][h][3]);
                    }
        }
        __syncthreads();     // all warps done with B (LDSM) before overwrite

        // ---- issue async load of next B tile + ssq (overlaps scan) ----
        if (t < 31) {
            int nmt = mt + 128;
#pragma unroll
            for (int i = 0; i < 16; i++) {
                int u = tid + 128 * i;
                int row = u >> 4, c = u & 15;
                CP_ASYNC16(sbase + OFF_B + row * 272 + c * 16,
                           xsrc + (size_t)(bbase + nmt + row) * 256 + c * 16);
            }
            CP_ASYNC4(sbase + OFF_SSQ + tid * 4, &g_sq[bbase + nmt + tid]);
            CP_COMMIT();
        }
        __syncwarp();

        // ---- scan: lane owns local row `lane` (64 cols) ----
        ull pend = 0;
#pragma unroll
        for (int i = 0; i < 32; i++) {
            float2 d = *reinterpret_cast<const float2*>(Drow + 2 * i);
            if (d.x > kthd) pend |= (1ull << (2 * i));
            if (d.y > kthd) pend |= (1ull << (2 * i + 1));
        }
        while (__any_sync(0xffffffffu, pend != 0ull)) {
            if (pend) {
                int slot = __ffsll(pend) - 1;
                pend &= pend - 1;
                float key = Drow[slot];
                if (key > kthd) {
                    int idx = mt + cg * 64 + slot;
                    uint32_t u = __float_as_uint(key);
                    uint32_t okey = (u & 0x80000000u) ? ~u : (u | 0x80000000u);
                    ull packed = ((ull)okey << 32) | (uint32_t)(~(uint32_t)idx);
                    sTop[kpos * 128 + tid] = packed;
                    ull mn = sTop[tid]; int mp = 0;
#pragma unroll
                    for (int j = 1; j < 20; j++) {
                        ull v = sTop[j * 128 + tid];
                        if (v < mn) { mn = v; mp = j; }
                    }
                    kpos = mp;
                    uint32_t hi = (uint32_t)(mn >> 32);
                    uint32_t u2 = (hi & 0x80000000u) ? (hi ^ 0x80000000u) : ~hi;
                    kthd = __uint_as_float(u2);
                }
            }
        }
    }

    __syncthreads();
    // ---- merge: cg==0 warps merge own list with partner (tid+32, cg==1) ----
    if (cg == 0) {
        int row_pt = bbase + r0 + rg * 32 + lane;
        int* op = g_idx + (size_t)row_pt * KK;
#pragma unroll 1
        for (int j = 0; j < KK; j++) {
            ull best = 0; int bp = 0;
#pragma unroll 1
            for (int q = 0; q < 40; q++) {
                ull v = (q < 20) ? sTop[q * 128 + tid] : sTop[(q - 20) * 128 + tid + 32];
                if (v > best) { best = v; bp = q; }
            }
            op[j] = (int)(~(uint32_t)best);
            if (bp < 20) sTop[bp * 128 + tid] = 0;
            else sTop[(bp - 20) * 128 + tid + 32] = 0;
        }
    }
}

// ---------------- D: gather p[idx]+q, max/min over k, BN partial sums ----------------
__global__ void k_gather() {
    int tid = threadIdx.x;  // 256
    int g = tid >> 6, o = tid & 63;
    float psum = 0.f, psq = 0.f;
#pragma unroll 1
    for (int i = 0; i < 8; i++) {
        int point = blockIdx.x * 32 + i * 4 + g;
        int b = point >> 12;
        const int* ix = g_idx + (size_t)point * KK;
        float qv = g_q[(size_t)point * OO + o];
        const float* pb = g_p + (((size_t)b) << 12) * OO;
        float mx = -FLT_MAX, mn = FLT_MAX;
#pragma unroll
        for (int k = 0; k < KK; k++) {
            int j = ix[k];
            float y = pb[(size_t)j * OO + o] + qv;
            mx = fmaxf(mx, y);
            mn = fminf(mn, y);
            psum += y;
            psq = fmaf(y, y, psq);
        }
        g_ymax[(size_t)point * OO + o] = mx;
        g_ymin[(size_t)point * OO + o] = mn;
    }
    __shared__ float ss[256], s2[256];
    ss[tid] = psum; s2[tid] = psq;
    __syncthreads();
    if (tid < 64) {
        float a = ss[tid] + ss[tid + 64] + ss[tid + 128] + ss[tid + 192];
        float c = s2[tid] + s2[tid + 64] + s2[tid + 128] + s2[tid + 192];
        g_part[(size_t)blockIdx.x * 128 + tid] = a;
        g_part[(size_t)blockIdx.x * 128 + 64 + tid] = c;
    }
}

__global__ void k_reduce() {
    int i = blockIdx.x;
    int t = threadIdx.x;
    float s = 0.f;
    for (int blk = t; blk < DBLK; blk += 256) s += g_part[(size_t)blk * 128 + i];
    __shared__ float smr[256];
    smr[t] = s;
    __syncthreads();
    for (int wd = 128; wd > 0; wd >>= 1) {
        if (t < wd) smr[t] += smr[t + wd];
        __syncthreads();
    }
    if (t == 0) g_stats[i] = smr[0];
}

__global__ void k_out(const float* __restrict__ gamma, const float* __restrict__ beta,
                      float* __restrict__ out) {
    __shared__ float smT[OO][33];
    int b = blockIdx.y, n0 = blockIdx.x * 32;
    int tid = threadIdx.x;
    const float CNTf = (float)(BB * NN * KK);
#pragma unroll 1
    for (int i = tid; i < 32 * OO; i += 256) {
        int n = i >> 6, o = i & 63;
        float s = g_stats[o], s2v = g_stats[64 + o];
        float mean = s / CNTf;
        float var = s2v / CNTf - mean * mean;
        float rstd = rsqrtf(var + EPS);
        float gm = gamma[o];
        size_t yi = ((size_t)b * NN + n0 + n) * OO + o;
        float v = (gm >= 0.f) ? g_ymax[yi] : g_ymin[yi];
        float z = gm * (v - mean) * rstd + beta[o];
        z = (z >= 0.f) ? z : NEG_SLOPE * z;
        smT[o][n] = z;
    }
    __syncthreads();
#pragma unroll 1
    for (int i = tid; i < OO * 32; i += 256) {
        int o = i >> 5, n = i & 31;
        out[((size_t)b * OO + o) * NN + n0 + n] = smT[o][n];
    }
}

extern "C" void kernel_launch(void* const* d_in, const int* in_sizes, int n_in,
                              void* d_out, int out_size) {
    const float* inp = (const float*)d_in[0];
    const float* W = (const float*)d_in[1];
    const float* gamma = (const float*)d_in[2];
    const float* beta = (const float*)d_in[3];
    float* out = (float*)d_out;

    cudaFuncSetAttribute(k_knn_wmma, cudaFuncAttributeMaxDynamicSharedMemorySize, DYN_BYTES);

    k_transpose<<<dim3(NN / 32, CC / 32, BB), dim3(32, 8)>>>(inp);
    k_split<<<BB * NN * 4 / 256, 256>>>();
    k_pq<<<BB * NN / 128, 128>>>(W);
    k_knn_wmma<<<dim3(NN / 64, BB), 128, DYN_BYTES>>>();
    k_gather<<<DBLK, 256>>>();
    k_reduce<<<2 * OO, 256>>>();
    k_out<<<dim3(NN / 32, BB), 256>>>(gamma, beta, out);
}